// round 10
// baseline (speedup 1.0000x reference)
#include <cuda_runtime.h>
#include <cstdint>

// APoT (8-bit, m=2) quantizer, eval forward:
//   apos = |alpha| + 1e-5
//   a    = clamp(RN(x / apos), -1, 1)
//   q(a) = nearest codebook level, tie -> smaller value
//   out  = q(a) * apos
//
// Codebook positive levels are exactly {B + off}: B = 2^-e (e in [0,15]),
// off in {0} U {2^-k : 2^-15 <= 2^-k <= B}; min positive level 2^-15.
// Nearest-with-tie == round the exact fraction f = m - B (Sterbenz) to the
// nearest allowed power of two; tie direction from the sign bit s.
//
//   um = bits(min(|a|, 1))                      (FMNMX, abs as src-mod)
//   uB = um & 0x7F800000                        (binade base)
//   Bf = (uB >= 2^-15) ? B : 0                  (low binades: round m vs {0,2^-15})
//   f  = m - Bf                                 (exact FADD)
//   t  = bits(f) + 0x3FFFFF + s                 (pow2 rounding via mantissa carry)
//   off = (t <= 0x37BFFFFF) ? 0                 (below/at the 2^-16 tie -> 0)
//       : max(t & 0xFF800000, bits(2^-15))      (offset floor 2^-15)
//   v  = Bf + off (exact);  out = copysign(v) * apos
//
// Division: Markstein with r = __frcp_rn(apos): q0 = x*r; e = fma(-apos,q0,x);
// a = fma(e,r,q0) is the correctly rounded quotient == __fdiv_rn == reference.
//
// Geometry (champion, rounds 3-9): 4 front-batched LDG.E.128 [R+imm] per
// thread, 256-thread blocks, grid = tiles, .cs loads. This round's single
// delta: stores switched .cs -> .wt (write-through). Rationale: the kernel
// is pinned at the mixed R/W DRAM service floor; .cs stores reach DRAM as
// bursty dirty-L2 evictions that interleave poorly with the read stream
// (R/W turnaround). Write-through emits the write stream smoothly in issue
// order and keeps L2 clean for the read stream. Correctness-neutral.

__device__ __forceinline__ float apot_quant(float x, float apos, float r) {
    float q0 = x * r;
    float e  = fmaf(-apos, q0, x);
    float a  = fmaf(e, r, q0);

    unsigned ua = __float_as_uint(a);
    unsigned s  = ua >> 31;
    float    m  = fminf(fabsf(a), 1.0f);          // single FMNMX
    unsigned um = __float_as_uint(m);
    unsigned uB = um & 0x7F800000u;

    const unsigned C15 = 0x38000000u;             // bits(2^-15)
    float Bf = (uB >= C15) ? __uint_as_float(uB) : 0.0f;

    float    f  = m - Bf;                          // exact
    unsigned t  = __float_as_uint(f) + 0x3FFFFFu + s;
    unsigned rb = umax(t & 0xFF800000u, C15);
    unsigned off = (t <= 0x37BFFFFFu) ? 0u : rb;

    float v = Bf + __uint_as_float(off);           // exact codebook level
    unsigned uv = __float_as_uint(v) | (ua & 0x80000000u);
    return __uint_as_float(uv) * apos;
}

__device__ __forceinline__ float4 quant4(float4 v, float apos, float r) {
    float4 o;
    o.x = apot_quant(v.x, apos, r);
    o.y = apot_quant(v.y, apos, r);
    o.z = apot_quant(v.z, apos, r);
    o.w = apot_quant(v.w, apos, r);
    return o;
}

// Fast path: n divisible by 256*4*4 = 4096 elements per block.
__global__ void __launch_bounds__(256)
apot_fast(const float4* __restrict__ x4,
          const float* __restrict__ alpha,
          float4* __restrict__ o4)
{
    float apos = fabsf(__ldg(alpha)) + 1e-5f;
    float r    = __frcp_rn(apos);

    int base = blockIdx.x * (256 * 4) + threadIdx.x;

    float4 v0 = __ldcs(x4 + base);
    float4 v1 = __ldcs(x4 + base + 256);
    float4 v2 = __ldcs(x4 + base + 512);
    float4 v3 = __ldcs(x4 + base + 768);

    __stwt(o4 + base,       quant4(v0, apos, r));
    __stwt(o4 + base + 256, quant4(v1, apos, r));
    __stwt(o4 + base + 512, quant4(v2, apos, r));
    __stwt(o4 + base + 768, quant4(v3, apos, r));
}

// Generic fallback: grid-stride, bounds-checked, handles any n.
__global__ void __launch_bounds__(256)
apot_generic(const float* __restrict__ x,
             const float* __restrict__ alpha,
             float* __restrict__ out,
             int n)
{
    float apos = fabsf(__ldg(alpha)) + 1e-5f;
    float r    = __frcp_rn(apos);

    int n4      = n >> 2;
    int gtid    = blockIdx.x * blockDim.x + threadIdx.x;
    int gstride = gridDim.x * blockDim.x;

    const float4* __restrict__ x4 = reinterpret_cast<const float4*>(x);
    float4* __restrict__ o4       = reinterpret_cast<float4*>(out);

    for (int i = gtid; i < n4; i += gstride)
        __stwt(&o4[i], quant4(__ldcs(&x4[i]), apos, r));
    for (int i = (n4 << 2) + gtid; i < n; i += gstride)
        out[i] = apot_quant(x[i], apos, r);
}

extern "C" void kernel_launch(void* const* d_in, const int* in_sizes, int n_in,
                              void* d_out, int out_size)
{
    const float* x     = (const float*)d_in[0];   // x: fp32
    const float* alpha = (const float*)d_in[1];   // alpha: fp32 scalar
    // d_in[2] = codebook — deterministic APoT set, reproduced arithmetically.
    float* out = (float*)d_out;

    int n = in_sizes[0];
    const int ELEMS_PER_BLOCK = 256 * 4 * 4;      // 4096

    if (n > 0 && (n % ELEMS_PER_BLOCK) == 0) {
        int blocks = n / ELEMS_PER_BLOCK;         // 8192 for 4096x8192
        apot_fast<<<blocks, 256>>>((const float4*)x, alpha, (float4*)out);
    } else {
        int n4 = n >> 2;
        int blocks = (n4 + 256 * 2 - 1) / (256 * 2);
        if (blocks < 1) blocks = 1;
        apot_generic<<<blocks, 256>>>(x, alpha, out, n);
    }
}

// round 11
// speedup vs baseline: 1.0036x; 1.0036x over previous
#include <cuda_runtime.h>
#include <cstdint>

// APoT (8-bit, m=2) quantizer, eval forward:
//   apos = |alpha| + 1e-5
//   a    = clamp(RN(x / apos), -1, 1)
//   q(a) = nearest codebook level, tie -> smaller value
//   out  = q(a) * apos
//
// Codebook positive levels are exactly {B + off}: B = 2^-e (e in [0,15]),
// off in {0} U {2^-k : 2^-15 <= 2^-k <= B}; min positive level 2^-15.
// Nearest-with-tie == round the exact fraction f = m - B (Sterbenz) to the
// nearest allowed power of two; tie direction from the sign bit s.
//
//   um = bits(min(|a|, 1))                      (FMNMX, abs as src-mod)
//   uB = um & 0x7F800000                        (binade base)
//   Bf = (uB >= 2^-15) ? B : 0                  (low binades: round m vs {0,2^-15})
//   f  = m - Bf                                 (exact FADD)
//   t  = bits(f) + 0x3FFFFF + s                 (pow2 rounding via mantissa carry)
//   off = (t <= 0x37BFFFFF) ? 0                 (below/at the 2^-16 tie -> 0)
//       : max(t & 0xFF800000, bits(2^-15))      (offset floor 2^-15)
//   v  = Bf + off (exact);  out = copysign(v) * apos
//
// Division: Markstein with r = __frcp_rn(apos): q0 = x*r; e = fma(-apos,q0,x);
// a = fma(e,r,q0) is the correctly rounded quotient == __fdiv_rn == reference.
// -> bit-exact vs the JAX reference (rel_err 0.0 across all rounds).
//
// FINAL configuration (10-round sweep; champion measured 36.8 us ncu twice):
// 4 front-batched LDG.E.128 [R+imm] per thread, 256-thread blocks,
// grid = tiles, .cs loads AND stores. Falsified alternatives: 8x batching
// (38.1), persistent 1-wave grid (38.8), .cg loads (37.5), 512-thread
// blocks (38.4), .wt stores (38.1). The kernel is pinned at the mixed R/W
// HBM service floor: 268 MB/replay at ~7.3 TB/s effective; no SM pipe
// above ~50%; the LTS cap is path-independent so no staging/write-policy
// variant can exceed this.

__device__ __forceinline__ float apot_quant(float x, float apos, float r) {
    float q0 = x * r;
    float e  = fmaf(-apos, q0, x);
    float a  = fmaf(e, r, q0);

    unsigned ua = __float_as_uint(a);
    unsigned s  = ua >> 31;
    float    m  = fminf(fabsf(a), 1.0f);          // single FMNMX
    unsigned um = __float_as_uint(m);
    unsigned uB = um & 0x7F800000u;

    const unsigned C15 = 0x38000000u;             // bits(2^-15)
    float Bf = (uB >= C15) ? __uint_as_float(uB) : 0.0f;

    float    f  = m - Bf;                          // exact
    unsigned t  = __float_as_uint(f) + 0x3FFFFFu + s;
    unsigned rb = umax(t & 0xFF800000u, C15);
    unsigned off = (t <= 0x37BFFFFFu) ? 0u : rb;

    float v = Bf + __uint_as_float(off);           // exact codebook level
    unsigned uv = __float_as_uint(v) | (ua & 0x80000000u);
    return __uint_as_float(uv) * apos;
}

__device__ __forceinline__ float4 quant4(float4 v, float apos, float r) {
    float4 o;
    o.x = apot_quant(v.x, apos, r);
    o.y = apot_quant(v.y, apos, r);
    o.z = apot_quant(v.z, apos, r);
    o.w = apot_quant(v.w, apos, r);
    return o;
}

// Fast path: n divisible by 256*4*4 = 4096 elements per block.
// 4 float4 per thread at compile-time offsets -> 4 front-batched LDG.E.128
// [R+imm], 4 KB in flight per warp, 32 regs, ~8 CTA/SM.
__global__ void __launch_bounds__(256)
apot_fast(const float4* __restrict__ x4,
          const float* __restrict__ alpha,
          float4* __restrict__ o4)
{
    float apos = fabsf(__ldg(alpha)) + 1e-5f;
    float r    = __frcp_rn(apos);

    int base = blockIdx.x * (256 * 4) + threadIdx.x;

    float4 v0 = __ldcs(x4 + base);
    float4 v1 = __ldcs(x4 + base + 256);
    float4 v2 = __ldcs(x4 + base + 512);
    float4 v3 = __ldcs(x4 + base + 768);

    __stcs(o4 + base,       quant4(v0, apos, r));
    __stcs(o4 + base + 256, quant4(v1, apos, r));
    __stcs(o4 + base + 512, quant4(v2, apos, r));
    __stcs(o4 + base + 768, quant4(v3, apos, r));
}

// Generic fallback: grid-stride, bounds-checked, handles any n.
__global__ void __launch_bounds__(256)
apot_generic(const float* __restrict__ x,
             const float* __restrict__ alpha,
             float* __restrict__ out,
             int n)
{
    float apos = fabsf(__ldg(alpha)) + 1e-5f;
    float r    = __frcp_rn(apos);

    int n4      = n >> 2;
    int gtid    = blockIdx.x * blockDim.x + threadIdx.x;
    int gstride = gridDim.x * blockDim.x;

    const float4* __restrict__ x4 = reinterpret_cast<const float4*>(x);
    float4* __restrict__ o4       = reinterpret_cast<float4*>(out);

    for (int i = gtid; i < n4; i += gstride)
        __stcs(&o4[i], quant4(__ldcs(&x4[i]), apos, r));
    for (int i = (n4 << 2) + gtid; i < n; i += gstride)
        out[i] = apot_quant(x[i], apos, r);
}

extern "C" void kernel_launch(void* const* d_in, const int* in_sizes, int n_in,
                              void* d_out, int out_size)
{
    const float* x     = (const float*)d_in[0];   // x: fp32
    const float* alpha = (const float*)d_in[1];   // alpha: fp32 scalar
    // d_in[2] = codebook — deterministic APoT set, reproduced arithmetically.
    float* out = (float*)d_out;

    int n = in_sizes[0];
    const int ELEMS_PER_BLOCK = 256 * 4 * 4;      // 4096

    if (n > 0 && (n % ELEMS_PER_BLOCK) == 0) {
        int blocks = n / ELEMS_PER_BLOCK;         // 8192 for 4096x8192
        apot_fast<<<blocks, 256>>>((const float4*)x, alpha, (float4*)out);
    } else {
        int n4 = n >> 2;
        int blocks = (n4 + 256 * 2 - 1) / (256 * 2);
        if (blocks < 1) blocks = 1;
        apot_generic<<<blocks, 256>>>(x, alpha, out, n);
    }
}

// round 12
// speedup vs baseline: 1.0375x; 1.0338x over previous
#include <cuda_runtime.h>
#include <cstdint>

// APoT (8-bit, m=2) quantizer, eval forward:
//   apos = |alpha| + 1e-5
//   a    = clamp(RN(x / apos), -1, 1)
//   q(a) = nearest codebook level, tie -> smaller value
//   out  = q(a) * apos
//
// Codebook positive levels are exactly {B + off}: B = 2^-e (e in [0,15]),
// off in {0} U {2^-k : 2^-15 <= 2^-k <= B}; min positive level 2^-15.
// Nearest-with-tie == round the exact fraction f = m - B (Sterbenz) to the
// nearest allowed power of two; tie direction from the sign bit s.
//
//   um = bits(min(|a|, 1))                      (FMNMX, abs as src-mod)
//   uB = um & 0x7F800000                        (binade base)
//   Bf = (uB >= 2^-15) ? B : 0                  (low binades: round m vs {0,2^-15})
//   f  = m - Bf                                 (exact FADD)
//   t  = bits(f) + 0x3FFFFF + s                 (pow2 rounding via mantissa carry)
//   off = (t <= 0x37BFFFFF) ? 0                 (below/at the 2^-16 tie -> 0)
//       : max(t & 0xFF800000, bits(2^-15))      (offset floor 2^-15)
//   v  = Bf + off (exact);  out = copysign(v) * apos
//
// Division: Markstein with r = __frcp_rn(apos): q0 = x*r; e = fma(-apos,q0,x);
// a = fma(e,r,q0) is the correctly rounded quotient == __fdiv_rn == reference.
// -> bit-exact vs the JAX reference (rel_err 0.0 across all rounds).
//
// FINAL configuration (11-round sweep; champion ncu samples 36.8/36.8/37.8/
// 37.2): 4 front-batched LDG.E.128 [R+imm] per thread, 256-thread blocks,
// grid = tiles, .cs loads AND stores. Falsified alternatives: 8x batching
// (38.1), persistent 1-wave grid (38.8), .cg loads (37.5), 512-thread
// blocks (38.4), .wt stores (38.1). The kernel is pinned at the mixed R/W
// HBM service floor: 268 MB/replay at ~7.3 TB/s effective; no SM pipe
// above ~50%; the LTS cap is path-independent so no staging/write-policy
// variant can exceed this.

__device__ __forceinline__ float apot_quant(float x, float apos, float r) {
    float q0 = x * r;
    float e  = fmaf(-apos, q0, x);
    float a  = fmaf(e, r, q0);

    unsigned ua = __float_as_uint(a);
    unsigned s  = ua >> 31;
    float    m  = fminf(fabsf(a), 1.0f);          // single FMNMX
    unsigned um = __float_as_uint(m);
    unsigned uB = um & 0x7F800000u;

    const unsigned C15 = 0x38000000u;             // bits(2^-15)
    float Bf = (uB >= C15) ? __uint_as_float(uB) : 0.0f;

    float    f  = m - Bf;                          // exact
    unsigned t  = __float_as_uint(f) + 0x3FFFFFu + s;
    unsigned rb = umax(t & 0xFF800000u, C15);
    unsigned off = (t <= 0x37BFFFFFu) ? 0u : rb;

    float v = Bf + __uint_as_float(off);           // exact codebook level
    unsigned uv = __float_as_uint(v) | (ua & 0x80000000u);
    return __uint_as_float(uv) * apos;
}

__device__ __forceinline__ float4 quant4(float4 v, float apos, float r) {
    float4 o;
    o.x = apot_quant(v.x, apos, r);
    o.y = apot_quant(v.y, apos, r);
    o.z = apot_quant(v.z, apos, r);
    o.w = apot_quant(v.w, apos, r);
    return o;
}

// Fast path: n divisible by 256*4*4 = 4096 elements per block.
// 4 float4 per thread at compile-time offsets -> 4 front-batched LDG.E.128
// [R+imm], 4 KB in flight per warp, 32 regs, ~8 CTA/SM.
__global__ void __launch_bounds__(256)
apot_fast(const float4* __restrict__ x4,
          const float* __restrict__ alpha,
          float4* __restrict__ o4)
{
    float apos = fabsf(__ldg(alpha)) + 1e-5f;
    float r    = __frcp_rn(apos);

    int base = blockIdx.x * (256 * 4) + threadIdx.x;

    float4 v0 = __ldcs(x4 + base);
    float4 v1 = __ldcs(x4 + base + 256);
    float4 v2 = __ldcs(x4 + base + 512);
    float4 v3 = __ldcs(x4 + base + 768);

    __stcs(o4 + base,       quant4(v0, apos, r));
    __stcs(o4 + base + 256, quant4(v1, apos, r));
    __stcs(o4 + base + 512, quant4(v2, apos, r));
    __stcs(o4 + base + 768, quant4(v3, apos, r));
}

// Generic fallback: grid-stride, bounds-checked, handles any n.
__global__ void __launch_bounds__(256)
apot_generic(const float* __restrict__ x,
             const float* __restrict__ alpha,
             float* __restrict__ out,
             int n)
{
    float apos = fabsf(__ldg(alpha)) + 1e-5f;
    float r    = __frcp_rn(apos);

    int n4      = n >> 2;
    int gtid    = blockIdx.x * blockDim.x + threadIdx.x;
    int gstride = gridDim.x * blockDim.x;

    const float4* __restrict__ x4 = reinterpret_cast<const float4*>(x);
    float4* __restrict__ o4       = reinterpret_cast<float4*>(out);

    for (int i = gtid; i < n4; i += gstride)
        __stcs(&o4[i], quant4(__ldcs(&x4[i]), apos, r));
    for (int i = (n4 << 2) + gtid; i < n; i += gstride)
        out[i] = apot_quant(x[i], apos, r);
}

extern "C" void kernel_launch(void* const* d_in, const int* in_sizes, int n_in,
                              void* d_out, int out_size)
{
    const float* x     = (const float*)d_in[0];   // x: fp32
    const float* alpha = (const float*)d_in[1];   // alpha: fp32 scalar
    // d_in[2] = codebook — deterministic APoT set, reproduced arithmetically.
    float* out = (float*)d_out;

    int n = in_sizes[0];
    const int ELEMS_PER_BLOCK = 256 * 4 * 4;      // 4096

    if (n > 0 && (n % ELEMS_PER_BLOCK) == 0) {
        int blocks = n / ELEMS_PER_BLOCK;         // 8192 for 4096x8192
        apot_fast<<<blocks, 256>>>((const float4*)x, alpha, (float4*)out);
    } else {
        int n4 = n >> 2;
        int blocks = (n4 + 256 * 2 - 1) / (256 * 2);
        if (blocks < 1) blocks = 1;
        apot_generic<<<blocks, 256>>>(x, alpha, out, n);
    }
}